// round 9
// baseline (speedup 1.0000x reference)
#include <cuda_runtime.h>
#include <math.h>
#include <cstdint>

#define N_TOK 16384
#define DMODEL 896
#define KMAX 3584   // [h | alpha*u | ug | h*ug]
#define INV_SQRT_D 0.03340766f
#define QMAX 16256.0f   // 127*128

// ---------------- scratch ----------------
__device__ float g_logit_part[N_TOK * 8];
__device__ float g_logit[N_TOK];
__device__ float g_sA[N_TOK];
__device__ float g_sWa[DMODEL], g_sWg[DMODEL], g_sWf[DMODEL];
__device__ __align__(16) int8_t g_A1[(size_t)N_TOK * KMAX];
__device__ __align__(16) int8_t g_A0[(size_t)N_TOK * KMAX];
__device__ __align__(16) int8_t g_Wa1[DMODEL * DMODEL],     g_Wa0[DMODEL * DMODEL];
__device__ __align__(16) int8_t g_Wg1[DMODEL * 2 * DMODEL], g_Wg0[DMODEL * 2 * DMODEL];
__device__ __align__(16) int8_t g_Wf1[DMODEL * 3 * DMODEL], g_Wf0[DMODEL * 3 * DMODEL];

// ---------------- helpers ----------------
static __device__ __forceinline__ uint32_t smem_u32(const void* p) {
    uint32_t a;
    asm("{ .reg .u64 t; cvta.to.shared.u64 t, %1; cvt.u32.u64 %0, t; }" : "=r"(a) : "l"(p));
    return a;
}
static __device__ __forceinline__ void cp16(uint32_t s, const void* g) {
    asm volatile("cp.async.cg.shared.global [%0], [%1], 16;" :: "r"(s), "l"(g));
}
#define CP_COMMIT() asm volatile("cp.async.commit_group;" ::: "memory")
#define CP_WAIT0()  asm volatile("cp.async.wait_group 0;" ::: "memory")

static __device__ __forceinline__ void ldmx4(uint32_t* r, uint32_t addr) {
    asm volatile("ldmatrix.sync.aligned.m8n8.x4.shared.b16 {%0,%1,%2,%3}, [%4];"
        : "=r"(r[0]), "=r"(r[1]), "=r"(r[2]), "=r"(r[3]) : "r"(addr));
}
static __device__ __forceinline__ void imma(int* c, const uint32_t* a, uint32_t b0, uint32_t b1) {
    asm volatile("mma.sync.aligned.m16n8k32.row.col.s32.s8.s8.s32 "
        "{%0,%1,%2,%3}, {%4,%5,%6,%7}, {%8,%9}, {%0,%1,%2,%3};"
        : "+r"(c[0]), "+r"(c[1]), "+r"(c[2]), "+r"(c[3])
        : "r"(a[0]), "r"(a[1]), "r"(a[2]), "r"(a[3]), "r"(b0), "r"(b1));
}

// quantize 4 floats into 4 hi-limb int8 (p1) and 4 lo-limb int8 (p0)
static __device__ __forceinline__ void quant4(float4 v, float inv, uint32_t& p1, uint32_t& p0) {
    float q0 = v.x * inv, q1 = v.y * inv, q2 = v.z * inv, q3 = v.w * inv;
    int a0 = __float2int_rn(q0 * 0.0078125f), a1 = __float2int_rn(q1 * 0.0078125f);
    int a2 = __float2int_rn(q2 * 0.0078125f), a3 = __float2int_rn(q3 * 0.0078125f);
    int b0 = __float2int_rn(q0 - 128.f * a0), b1 = __float2int_rn(q1 - 128.f * a1);
    int b2 = __float2int_rn(q2 - 128.f * a2), b3 = __float2int_rn(q3 - 128.f * a3);
    p1 = (a0 & 0xff) | ((a1 & 0xff) << 8) | ((a2 & 0xff) << 16) | ((uint32_t)(a3 & 0xff) << 24);
    p0 = (b0 & 0xff) | ((b1 & 0xff) << 8) | ((b2 & 0xff) << 16) | ((uint32_t)(b3 & 0xff) << 24);
}
// quantize 2 floats -> 2B per plane
static __device__ __forceinline__ void quant2(float2 v, float inv, uint16_t& p1, uint16_t& p0) {
    float qx = v.x * inv, qy = v.y * inv;
    int x1 = __float2int_rn(qx * 0.0078125f), y1 = __float2int_rn(qy * 0.0078125f);
    int x0 = __float2int_rn(qx - 128.f * x1), y0 = __float2int_rn(qy - 128.f * y1);
    p1 = (uint16_t)((x1 & 0xff) | ((y1 & 0xff) << 8));
    p0 = (uint16_t)((x0 & 0xff) | ((y0 & 0xff) << 8));
}
static __device__ __forceinline__ float wmax_reduce(float m) {
    m = fmaxf(m, __shfl_xor_sync(0xffffffffu, m, 16));
    m = fmaxf(m, __shfl_xor_sync(0xffffffffu, m, 8));
    m = fmaxf(m, __shfl_xor_sync(0xffffffffu, m, 4));
    m = fmaxf(m, __shfl_xor_sync(0xffffffffu, m, 2));
    m = fmaxf(m, __shfl_xor_sync(0xffffffffu, m, 1));
    return m;
}

// ---------------- conversion: one warp per A-row (16384) then per W-col (2688) ----------------
#define CONV_WARPS (N_TOK + 3 * DMODEL)
__global__ void k_conv(const float* __restrict__ h, const float* __restrict__ u,
                       const float* __restrict__ wa, const float* __restrict__ wg,
                       const float* __restrict__ wf) {
    const int w = (blockIdx.x * blockDim.x + threadIdx.x) >> 5;
    const int l = threadIdx.x & 31;
    if (w < N_TOK) {
        const float* hr = h + (size_t)w * DMODEL;
        const float* ur = u + (size_t)w * DMODEL;
        float4 hv[7], uv[7];
        float m = 0.f;
#pragma unroll
        for (int j = 0; j < 7; j++) {
            hv[j] = *(const float4*)(hr + (j * 32 + l) * 4);
            uv[j] = *(const float4*)(ur + (j * 32 + l) * 4);
            m = fmaxf(m, fmaxf(fmaxf(fabsf(hv[j].x), fabsf(hv[j].y)), fmaxf(fabsf(hv[j].z), fabsf(hv[j].w))));
            m = fmaxf(m, fmaxf(fmaxf(fabsf(uv[j].x), fabsf(uv[j].y)), fmaxf(fabsf(uv[j].z), fabsf(uv[j].w))));
            m = fmaxf(m, fmaxf(fmaxf(fabsf(hv[j].x * uv[j].x), fabsf(hv[j].y * uv[j].y)),
                               fmaxf(fabsf(hv[j].z * uv[j].z), fabsf(hv[j].w * uv[j].w))));
        }
        m = wmax_reduce(m);
        const float sval = fmaxf(m, 1e-30f) * (1.f / QMAX);
        const float inv = 1.f / sval;
        if (l == 0) g_sA[w] = sval;
        const size_t base = (size_t)w * KMAX;
#pragma unroll
        for (int j = 0; j < 7; j++) {
            const int c4 = (j * 32 + l) * 4;
            uint32_t p1, p0;
            quant4(hv[j], inv, p1, p0);
            *(uint32_t*)(g_A1 + base + c4) = p1;
            *(uint32_t*)(g_A0 + base + c4) = p0;
            quant4(uv[j], inv, p1, p0);
            *(uint32_t*)(g_A1 + base + DMODEL + c4) = p1;
            *(uint32_t*)(g_A0 + base + DMODEL + c4) = p0;
        }
    } else if (w < CONV_WARPS) {
        int c = w - N_TOK;
        const float* src; int8_t *p1g, *p0g; float* sout; int K;
        if (c < DMODEL)          { src = wa + (size_t)c * DMODEL;                 p1g = g_Wa1 + (size_t)c * DMODEL;       p0g = g_Wa0 + (size_t)c * DMODEL;       sout = g_sWa + c; K = DMODEL; }
        else if (c < 2 * DMODEL) { c -= DMODEL; src = wg + (size_t)c * 2 * DMODEL; p1g = g_Wg1 + (size_t)c * 2 * DMODEL; p0g = g_Wg0 + (size_t)c * 2 * DMODEL; sout = g_sWg + c; K = 2 * DMODEL; }
        else                     { c -= 2 * DMODEL; src = wf + (size_t)c * 3 * DMODEL; p1g = g_Wf1 + (size_t)c * 3 * DMODEL; p0g = g_Wf0 + (size_t)c * 3 * DMODEL; sout = g_sWf + c; K = 3 * DMODEL; }
        float m = 0.f;
        for (int j = l * 4; j < K; j += 128) {
            float4 v = *(const float4*)(src + j);
            m = fmaxf(m, fmaxf(fmaxf(fabsf(v.x), fabsf(v.y)), fmaxf(fabsf(v.z), fabsf(v.w))));
        }
        m = wmax_reduce(m);
        const float sval = fmaxf(m, 1e-30f) * (1.f / QMAX);
        const float inv = 1.f / sval;
        if (l == 0) *sout = sval;
        for (int j = l * 4; j < K; j += 128) {
            uint32_t p1, p0;
            quant4(*(const float4*)(src + j), inv, p1, p0);
            *(uint32_t*)(p1g + j) = p1;
            *(uint32_t*)(p0g + j) = p0;
        }
    }
}

// one warp per row: reduce logit partials, compute alpha, write quantized alpha*u into A[896:1792]
__global__ void k_alpha(const float* __restrict__ u) {
    const int row = blockIdx.x * 8 + (threadIdx.x >> 5);
    const int l = threadIdx.x & 31;
    float s = (l < 7) ? g_logit_part[(size_t)row * 8 + l] : 0.f;
    s += __shfl_xor_sync(0xffffffffu, s, 1);
    s += __shfl_xor_sync(0xffffffffu, s, 2);
    s += __shfl_xor_sync(0xffffffffu, s, 4);
    s = __shfl_sync(0xffffffffu, s, 0);
    if (l == 0) g_logit[row] = s;
    const float a = 1.f / (1.f + __expf(-s * INV_SQRT_D));
    const float inv = 1.f / g_sA[row];
    const float* ur = u + (size_t)row * DMODEL;
    const size_t base = (size_t)row * KMAX + DMODEL;
#pragma unroll
    for (int j = 0; j < 7; j++) {
        const int c4 = (j * 32 + l) * 4;
        float4 v = *(const float4*)(ur + c4);
        v.x *= a; v.y *= a; v.z *= a; v.w *= a;
        uint32_t p1, p0;
        quant4(v, inv, p1, p0);
        *(uint32_t*)(g_A1 + base + c4) = p1;
        *(uint32_t*)(g_A0 + base + c4) = p0;
    }
}

// ---------------- int8x2-limb IMMA GEMM: 128x128 CTA, 512 thr, warp tile 32x32 ----------------
#define ROWB    48
#define TILE_B  (128 * ROWB)      // 6144
#define T_A1    0
#define T_A0    TILE_B
#define T_B1    (2 * TILE_B)
#define T_B0    (3 * TILE_B)
#define STAGE_STRIDE 32768
#define SMEM_BYTES (STAGE_STRIDE + 4 * TILE_B)   // 57344

template <int MODE>
__global__ void __launch_bounds__(512, 1) igemm(
    const float* __restrict__ hmat, const float* __restrict__ umat,
    const int8_t* __restrict__ W1, const int8_t* __restrict__ W0,
    const float* __restrict__ sW, const float* __restrict__ bias,
    float* __restrict__ dst)
{
    constexpr int K = (MODE == 0) ? 896 : (MODE == 1 ? 1792 : 2688);
    constexpr int AOFF = (MODE == 0) ? 896 : 0;
    constexpr int NT = K / 32;
    extern __shared__ __align__(16) char smem[];
    const uint32_t sb = smem_u32(smem);

    const int tid = threadIdx.x, wid = tid >> 5, l = tid & 31;
    const int cb = blockIdx.x, rb = blockIdx.y;
    const int row0 = rb * 128, col0 = cb * 128;

    // ---- loader: thread -> (tile, row); 2 cp16 per stage ----
    const int lt = tid >> 7, r = tid & 127;
    const int8_t* gsrc;
    if (lt == 0)      gsrc = g_A1 + (size_t)(row0 + r) * KMAX + AOFF;
    else if (lt == 1) gsrc = g_A0 + (size_t)(row0 + r) * KMAX + AOFF;
    else if (lt == 2) gsrc = W1 + (size_t)(col0 + r) * K;
    else              gsrc = W0 + (size_t)(col0 + r) * K;
    const uint32_t sdst = sb + (uint32_t)(lt * TILE_B + r * ROWB);

    int nextk = 0;
    auto issue = [&]() {
        const uint32_t so = sdst + (uint32_t)((nextk >> 5) & 1) * STAGE_STRIDE;
        cp16(so, gsrc);
        cp16(so + 16, gsrc + 16);
        CP_COMMIT();
        nextk += 32;
        int adv = 32;
        if (MODE == 2 && nextk == DMODEL && lt < 2) adv += DMODEL;  // skip alpha*u slot
        gsrc += adv;
    };

    // ---- warp tiling: 4 (M) x 4 (N); warp tile 32x32 ----
    const int wM = wid & 3, wN = wid >> 2;
    const int wMr = wM * 32, wNc = wN * 32;
    const int lq = l >> 2, lr = l & 3;

    int S11[2][4][4], S12[2][4][4];
#pragma unroll
    for (int a = 0; a < 2; a++)
#pragma unroll
        for (int b = 0; b < 4; b++)
#pragma unroll
            for (int c = 0; c < 4; c++) { S11[a][b][c] = 0; S12[a][b][c] = 0; }

    const uint32_t kHalf = (uint32_t)((l >> 4) * 16);
    const uint32_t a1b = sb + T_A1 + (uint32_t)((wMr + (l & 15)) * ROWB) + kHalf;
    const uint32_t a0b = a1b + TILE_B;
    const uint32_t b1b = sb + T_B1 + (uint32_t)((wNc + (l & 15)) * ROWB) + kHalf;
    const uint32_t b0b = b1b + TILE_B;

    issue();
    for (int t = 0; t < NT; t++) {
        CP_WAIT0();
        __syncthreads();
        if (t + 1 < NT) issue();

        const uint32_t stb = (uint32_t)((t & 1) << 15);
        uint32_t b1f[2][4], b0f[2][4];
#pragma unroll
        for (int nj = 0; nj < 2; nj++) {
            ldmx4(b1f[nj], b1b + stb + (uint32_t)(nj * 16 * ROWB));
            ldmx4(b0f[nj], b0b + stb + (uint32_t)(nj * 16 * ROWB));
        }
#pragma unroll
        for (int mi = 0; mi < 2; mi++) {
            uint32_t a1f[4], a0f[4];
            ldmx4(a1f, a1b + stb + (uint32_t)(mi * 16 * ROWB));
            ldmx4(a0f, a0b + stb + (uint32_t)(mi * 16 * ROWB));
#pragma unroll
            for (int nj = 0; nj < 2; nj++) {
                imma(S11[mi][nj * 2 + 0], a1f, b1f[nj][0], b1f[nj][2]);
                imma(S11[mi][nj * 2 + 1], a1f, b1f[nj][1], b1f[nj][3]);
            }
#pragma unroll
            for (int nj = 0; nj < 2; nj++) {
                imma(S12[mi][nj * 2 + 0], a1f, b0f[nj][0], b0f[nj][2]);
                imma(S12[mi][nj * 2 + 1], a1f, b0f[nj][1], b0f[nj][3]);
            }
#pragma unroll
            for (int nj = 0; nj < 2; nj++) {
                imma(S12[mi][nj * 2 + 0], a0f, b1f[nj][0], b1f[nj][2]);
                imma(S12[mi][nj * 2 + 1], a0f, b1f[nj][1], b1f[nj][3]);
            }
        }
        __syncthreads();
    }

    // ---- epilogues: z = (16384*S11 + 128*S12) * sA[r]*sW[c] + bias ----
    if (MODE == 0) {
        __syncthreads();
        float* red = (float*)smem;  // [128][4]
#pragma unroll
        for (int mi = 0; mi < 2; mi++) {
#pragma unroll
            for (int rr = 0; rr < 2; rr++) {
                const int rloc = wMr + mi * 16 + lq + rr * 8;
                const float sa = g_sA[row0 + rloc];
                const float* hrow = hmat + (size_t)(row0 + rloc) * DMODEL + col0 + wNc;
                float s = 0.f;
#pragma unroll
                for (int n8 = 0; n8 < 4; n8++) {
                    const int cc = n8 * 8 + lr * 2;
                    float2 h2 = *(const float2*)(hrow + cc);
                    float2 bb = *(const float2*)(bias + col0 + wNc + cc);
                    float2 sw = *(const float2*)(sW + col0 + wNc + cc);
                    float z0 = fmaf(16384.f, (float)S11[mi][n8][rr * 2 + 0], 128.f * (float)S12[mi][n8][rr * 2 + 0]) * (sa * sw.x) + bb.x;
                    float z1 = fmaf(16384.f, (float)S11[mi][n8][rr * 2 + 1], 128.f * (float)S12[mi][n8][rr * 2 + 1]) * (sa * sw.y) + bb.y;
                    s += h2.x * z0 + h2.y * z1;
                }
                s += __shfl_xor_sync(0xffffffffu, s, 1);
                s += __shfl_xor_sync(0xffffffffu, s, 2);
                if (lr == 0) red[rloc * 4 + wN] = s;
            }
        }
        __syncthreads();
        if (tid < 128) {
            float s = red[tid * 4] + red[tid * 4 + 1] + red[tid * 4 + 2] + red[tid * 4 + 3];
            g_logit_part[(size_t)(row0 + tid) * 8 + cb] = s;
        }
    } else if (MODE == 1) {
#pragma unroll
        for (int mi = 0; mi < 2; mi++) {
#pragma unroll
            for (int rr = 0; rr < 2; rr++) {
                const int rg = row0 + wMr + mi * 16 + lq + rr * 8;
                const float sa = g_sA[rg];
                const float inv = 1.f / sa;
                const float al = 1.f / (1.f + __expf(-g_logit[rg] * INV_SQRT_D));
                const float* urow = umat + (size_t)rg * DMODEL + col0 + wNc;
                const float* hrow = hmat + (size_t)rg * DMODEL + col0 + wNc;
                const size_t base1 = (size_t)rg * KMAX + 2 * DMODEL + col0 + wNc;  // ug
                const size_t base2 = (size_t)rg * KMAX + 3 * DMODEL + col0 + wNc;  // h*ug
#pragma unroll
                for (int n8 = 0; n8 < 4; n8++) {
                    const int cc = n8 * 8 + lr * 2;
                    float2 bb = *(const float2*)(bias + col0 + wNc + cc);
                    float2 sw = *(const float2*)(sW + col0 + wNc + cc);
                    float2 u2 = *(const float2*)(urow + cc);
                    float2 h2 = *(const float2*)(hrow + cc);
                    float z0 = fmaf(16384.f, (float)S11[mi][n8][rr * 2 + 0], 128.f * (float)S12[mi][n8][rr * 2 + 0]) * (sa * sw.x) + bb.x;
                    float z1 = fmaf(16384.f, (float)S11[mi][n8][rr * 2 + 1], 128.f * (float)S12[mi][n8][rr * 2 + 1]) * (sa * sw.y) + bb.y;
                    float2 o;
                    o.x = al * u2.x / (1.f + __expf(-z0));
                    o.y = al * u2.y / (1.f + __expf(-z1));
                    uint16_t p1, p0;
                    quant2(o, inv, p1, p0);
                    *(uint16_t*)(g_A1 + base1 + cc) = p1;
                    *(uint16_t*)(g_A0 + base1 + cc) = p0;
                    quant2(make_float2(o.x * h2.x, o.y * h2.y), inv, p1, p0);
                    *(uint16_t*)(g_A1 + base2 + cc) = p1;
                    *(uint16_t*)(g_A0 + base2 + cc) = p0;
                }
            }
        }
    } else {
#pragma unroll
        for (int mi = 0; mi < 2; mi++) {
#pragma unroll
            for (int rr = 0; rr < 2; rr++) {
                const int rg = row0 + wMr + mi * 16 + lq + rr * 8;
                const float sa = g_sA[rg];
                float* orow = dst + (size_t)rg * DMODEL + col0 + wNc;
#pragma unroll
                for (int n8 = 0; n8 < 4; n8++) {
                    const int cc = n8 * 8 + lr * 2;
                    float2 bb = *(const float2*)(bias + col0 + wNc + cc);
                    float2 sw = *(const float2*)(sW + col0 + wNc + cc);
                    float z0 = fmaf(16384.f, (float)S11[mi][n8][rr * 2 + 0], 128.f * (float)S12[mi][n8][rr * 2 + 0]) * (sa * sw.x) + bb.x;
                    float z1 = fmaf(16384.f, (float)S11[mi][n8][rr * 2 + 1], 128.f * (float)S12[mi][n8][rr * 2 + 1]) * (sa * sw.y) + bb.y;
                    float2 o;
                    o.x = 0.5f * z0 * (1.f + erff(z0 * 0.70710678f));
                    o.y = 0.5f * z1 * (1.f + erff(z1 * 0.70710678f));
                    *(float2*)(orow + cc) = o;
                }
            }
        }
    }
}

extern "C" void kernel_launch(void* const* d_in, const int* in_sizes, int n_in,
                              void* d_out, int out_size) {
    const float* h_t   = (const float*)d_in[0];
    const float* u_t   = (const float*)d_in[1];
    const float* W_a_w = (const float*)d_in[4];
    const float* W_a_b = (const float*)d_in[5];
    const float* W_g_w = (const float*)d_in[6];
    const float* W_g_b = (const float*)d_in[7];
    const float* W_f_w = (const float*)d_in[8];
    const float* W_f_b = (const float*)d_in[9];
    float* out = (float*)d_out;

    cudaFuncSetAttribute(igemm<0>, cudaFuncAttributeMaxDynamicSharedMemorySize, SMEM_BYTES);
    cudaFuncSetAttribute(igemm<1>, cudaFuncAttributeMaxDynamicSharedMemorySize, SMEM_BYTES);
    cudaFuncSetAttribute(igemm<2>, cudaFuncAttributeMaxDynamicSharedMemorySize, SMEM_BYTES);

    int8_t *Wa1, *Wa0, *Wg1, *Wg0, *Wf1, *Wf0;
    float *sWa, *sWg, *sWf;
    cudaGetSymbolAddress((void**)&Wa1, g_Wa1); cudaGetSymbolAddress((void**)&Wa0, g_Wa0);
    cudaGetSymbolAddress((void**)&Wg1, g_Wg1); cudaGetSymbolAddress((void**)&Wg0, g_Wg0);
    cudaGetSymbolAddress((void**)&Wf1, g_Wf1); cudaGetSymbolAddress((void**)&Wf0, g_Wf0);
    cudaGetSymbolAddress((void**)&sWa, g_sWa); cudaGetSymbolAddress((void**)&sWg, g_sWg);
    cudaGetSymbolAddress((void**)&sWf, g_sWf);

    dim3 grid(DMODEL / 128, N_TOK / 128);  // (7, 128)
    const int nConvBlocks = (CONV_WARPS + 7) / 8;  // 8 warps per 256-thr block

    // 5 launches; #4 (igemm<1>) is the ncu-captured launch
    k_conv<<<nConvBlocks, 256>>>(h_t, u_t, W_a_w, W_g_w, W_f_w);                     // 1
    igemm<0><<<grid, 512, SMEM_BYTES>>>(h_t, u_t, Wa1, Wa0, sWa, W_a_b, nullptr);    // 2
    k_alpha<<<N_TOK / 8, 256>>>(u_t);                                                // 3
    igemm<1><<<grid, 512, SMEM_BYTES>>>(h_t, u_t, Wg1, Wg0, sWg, W_g_b, nullptr);    // 4
    igemm<2><<<grid, 512, SMEM_BYTES>>>(h_t, u_t, Wf1, Wf0, sWf, W_f_b, out);        // 5
}

// round 10
// speedup vs baseline: 3.0591x; 3.0591x over previous
#include <cuda_runtime.h>
#include <cuda_fp16.h>
#include <math.h>
#include <cstdint>

#define N_TOK 16384
#define DMODEL 896
#define KMAX 3584   // [h | alpha*u | ug | h*ug]
#define INV_SQRT_D 0.03340766f

// ---------------- scratch (device globals) ----------------
__device__ float g_logit_part[N_TOK * 8];
__device__ float g_logit[N_TOK];
__device__ __align__(16) __half g_A[(size_t)N_TOK * KMAX];                     // f16 activations
__device__ __align__(16) __half g_Wa1[DMODEL * DMODEL],     g_Wa0[DMODEL * DMODEL];
__device__ __align__(16) __half g_Wg1[DMODEL * 2 * DMODEL], g_Wg0[DMODEL * 2 * DMODEL];
__device__ __align__(16) __half g_Wf1[DMODEL * 3 * DMODEL], g_Wf0[DMODEL * 3 * DMODEL];

// ---------------- helpers ----------------
static __device__ __forceinline__ uint32_t smem_u32(const void* p) {
    uint32_t a;
    asm("{ .reg .u64 t; cvta.to.shared.u64 t, %1; cvt.u32.u64 %0, t; }" : "=r"(a) : "l"(p));
    return a;
}
static __device__ __forceinline__ void cp16(uint32_t s, const void* g) {
    asm volatile("cp.async.cg.shared.global [%0], [%1], 16;" :: "r"(s), "l"(g));
}
#define CP_COMMIT() asm volatile("cp.async.commit_group;" ::: "memory")
#define CP_WAIT0()  asm volatile("cp.async.wait_group 0;" ::: "memory")

static __device__ __forceinline__ void ldmx4(uint32_t* r, uint32_t addr) {
    asm volatile("ldmatrix.sync.aligned.m8n8.x4.shared.b16 {%0,%1,%2,%3}, [%4];"
        : "=r"(r[0]), "=r"(r[1]), "=r"(r[2]), "=r"(r[3]) : "r"(addr));
}
static __device__ __forceinline__ void mma16816(float* c, const uint32_t* a,
                                                uint32_t b0, uint32_t b1) {
    asm volatile("mma.sync.aligned.m16n8k16.row.col.f32.f16.f16.f32 "
        "{%0,%1,%2,%3}, {%4,%5,%6,%7}, {%8,%9}, {%0,%1,%2,%3};"
        : "+f"(c[0]), "+f"(c[1]), "+f"(c[2]), "+f"(c[3])
        : "r"(a[0]), "r"(a[1]), "r"(a[2]), "r"(a[3]), "r"(b0), "r"(b1));
}

// pack float4 -> 4 f16 (8 bytes)
static __device__ __forceinline__ void f16_store4(__half* dst, size_t idx, float4 v) {
    uint32_t p01, p23;
    asm("cvt.rn.f16x2.f32 %0, %1, %2;" : "=r"(p01) : "f"(v.y), "f"(v.x));
    asm("cvt.rn.f16x2.f32 %0, %1, %2;" : "=r"(p23) : "f"(v.w), "f"(v.z));
    *(uint2*)(dst + idx) = make_uint2(p01, p23);
}
static __device__ __forceinline__ void f16_store2(__half* dst, size_t idx, float2 v) {
    uint32_t p;
    asm("cvt.rn.f16x2.f32 %0, %1, %2;" : "=r"(p) : "f"(v.y), "f"(v.x));
    *(uint32_t*)(dst + idx) = p;
}
// split float4 into f16 hi + f16 residual lo
static __device__ __forceinline__ void f16_split4(__half* hi, __half* lo, size_t idx, float4 v) {
    __half hx = __float2half_rn(v.x), hy = __float2half_rn(v.y);
    __half hz = __float2half_rn(v.z), hw = __float2half_rn(v.w);
    float4 r = make_float4(v.x - __half2float(hx), v.y - __half2float(hy),
                           v.z - __half2float(hz), v.w - __half2float(hw));
    uint32_t h01, h23;
    asm("mov.b32 %0, {%1, %2};" : "=r"(h01) : "h"(__half_as_ushort(hx)), "h"(__half_as_ushort(hy)));
    asm("mov.b32 %0, {%1, %2};" : "=r"(h23) : "h"(__half_as_ushort(hz)), "h"(__half_as_ushort(hw)));
    *(uint2*)(hi + idx) = make_uint2(h01, h23);
    f16_store4(lo, 0, r);  // placeholder avoided below
}

// ---------------- fused conversion kernel ----------------
#define NA_ITEMS (N_TOK * 224 * 2)
#define NW_ITEMS (DMODEL * (DMODEL + 2 * DMODEL + 3 * DMODEL) / 4)
__global__ void k_conv_all(const float* __restrict__ h, const float* __restrict__ u,
                           const float* __restrict__ wa, const float* __restrict__ wg,
                           const float* __restrict__ wf) {
    int i = blockIdx.x * blockDim.x + threadIdx.x;
    const int half = N_TOK * 224;
    if (i < half) {
        int row = i / 224, c4 = (i % 224) * 4;
        f16_store4(g_A, (size_t)row * KMAX + c4,
                   *(const float4*)(h + (size_t)row * DMODEL + c4));
    } else if (i < 2 * half) {
        int j = i - half;
        int row = j / 224, c4 = (j % 224) * 4;
        f16_store4(g_A, (size_t)row * KMAX + DMODEL + c4,
                   *(const float4*)(u + (size_t)row * DMODEL + c4));
    } else {
        int j = i - 2 * half;
        const int n1 = DMODEL * DMODEL / 4;
        const int n2 = DMODEL * 2 * DMODEL / 4;
        const int n3 = DMODEL * 3 * DMODEL / 4;
        const float* src; __half *p1, *p0; int idx;
        if (j < n1)           { src = wa; p1 = g_Wa1; p0 = g_Wa0; idx = j; }
        else if (j < n1 + n2) { src = wg; p1 = g_Wg1; p0 = g_Wg0; idx = j - n1; }
        else if (j < n1 + n2 + n3) { src = wf; p1 = g_Wf1; p0 = g_Wf0; idx = j - n1 - n2; }
        else return;
        float4 v = ((const float4*)src)[idx];
        __half hx = __float2half_rn(v.x), hy = __float2half_rn(v.y);
        __half hz = __float2half_rn(v.z), hw = __float2half_rn(v.w);
        uint32_t h01, h23;
        asm("mov.b32 %0, {%1, %2};" : "=r"(h01) : "h"(__half_as_ushort(hx)), "h"(__half_as_ushort(hy)));
        asm("mov.b32 %0, {%1, %2};" : "=r"(h23) : "h"(__half_as_ushort(hz)), "h"(__half_as_ushort(hw)));
        *(uint2*)(p1 + (size_t)idx * 4) = make_uint2(h01, h23);
        f16_store4(p0, (size_t)idx * 4,
                   make_float4(v.x - __half2float(hx), v.y - __half2float(hy),
                               v.z - __half2float(hz), v.w - __half2float(hw)));
    }
}

// one warp per row: reduce logit partials, compute alpha, write f16 alpha*u into A[896:1792]
__global__ void k_alpha(const float* __restrict__ u) {
    const int row = blockIdx.x * 8 + (threadIdx.x >> 5);
    const int l = threadIdx.x & 31;
    float s = (l < 7) ? g_logit_part[(size_t)row * 8 + l] : 0.f;
    s += __shfl_xor_sync(0xffffffffu, s, 1);
    s += __shfl_xor_sync(0xffffffffu, s, 2);
    s += __shfl_xor_sync(0xffffffffu, s, 4);
    s = __shfl_sync(0xffffffffu, s, 0);
    if (l == 0) g_logit[row] = s;
    const float a = 1.f / (1.f + __expf(-s * INV_SQRT_D));
    const float* ur = u + (size_t)row * DMODEL;
    const size_t base = (size_t)row * KMAX + DMODEL;
#pragma unroll
    for (int j = 0; j < 7; j++) {
        const int c4 = (j * 32 + l) * 4;
        float4 v = *(const float4*)(ur + c4);
        v.x *= a; v.y *= a; v.z *= a; v.w *= a;
        f16_store4(g_A, base + c4, v);
    }
}

// ---------------- f16 2-pass HMMA GEMM (256 thr, 2x4 warps, 64x32 warp tile) ----------------
#define ROWB    80
#define TILE_B  (128 * ROWB)          // 10240
#define T_A     0
#define T_B1    TILE_B
#define T_B0    (2 * TILE_B)
#define STAGE_STRIDE 32768            // stage offset = (t&1)<<15
#define SMEM_BYTES (STAGE_STRIDE + 3 * TILE_B)   // 63488; 2 CTAs = 124KB

// MODE 0: K=896 (A = u slot). Epi: logit partials
// MODE 1: K=1792 (A=[h|alpha u]). Epi: ug -> A[1792:2688], h*ug -> A[2688:3584]
// MODE 2: K=2688 (A = {[0:896),[1792:3584)}). Epi: dst = gelu_erf(z)
template <int MODE>
__global__ void __launch_bounds__(256, 2) hgemm(
    const float* __restrict__ hmat, const float* __restrict__ umat,
    const __half* __restrict__ W1, const __half* __restrict__ W0,
    const float* __restrict__ bias, float* __restrict__ dst)
{
    constexpr int K = (MODE == 0) ? 896 : (MODE == 1 ? 1792 : 2688);
    constexpr int AOFF = (MODE == 0) ? 896 : 0;
    constexpr int NT = K / 32;
    extern __shared__ __align__(16) char smem[];
    const uint32_t sb = smem_u32(smem);

    const int tid = threadIdx.x, wid = tid >> 5, l = tid & 31;
    const int cb = blockIdx.x, rb = blockIdx.y;
    const int row0 = rb * 128, col0 = cb * 128;

    // ---- loader: each thread owns one smem row, 2 of 4 16B chunks (lc in {0,2}) ----
    const int lrow = tid >> 1, lc = (tid & 1) * 2;
    const __half* pA  = g_A + (size_t)(row0 + lrow) * KMAX + AOFF + lc * 8;
    const __half* pB1 = W1 + (size_t)(col0 + lrow) * K + lc * 8;
    const __half* pB0 = W0 + (size_t)(col0 + lrow) * K + lc * 8;
    const uint32_t sl = sb + (uint32_t)(lrow * ROWB + lc * 16);

    int nextk = 0;
    auto issue = [&]() {
        const uint32_t so = sl + (uint32_t)((nextk >> 5) & 1) * STAGE_STRIDE;
        cp16(so + T_A, pA);        cp16(so + T_A + 16, pA + 8);
        cp16(so + T_B1, pB1);      cp16(so + T_B1 + 16, pB1 + 8);
        cp16(so + T_B0, pB0);      cp16(so + T_B0 + 16, pB0 + 8);
        CP_COMMIT();
        nextk += 32;
        int adv = 32;
        if (MODE == 2 && nextk == DMODEL) adv += DMODEL;  // skip alpha*u slot
        pA += adv; pB1 += 32; pB0 += 32;
    };

    // ---- warp tiling: 2 (M) x 4 (N); warp tile 64x32 ----
    const int wM = wid & 1, wN = wid >> 1;
    const int wMr = wM * 64, wNc = wN * 32;
    const int lq = l >> 2, lr = l & 3;

    float acc[4][4][4];
#pragma unroll
    for (int a = 0; a < 4; a++)
#pragma unroll
        for (int b = 0; b < 4; b++)
#pragma unroll
            for (int c = 0; c < 4; c++) acc[a][b][c] = 0.f;

    const uint32_t kHalf = (uint32_t)((l >> 4) * 16);
    const uint32_t aB  = sb + T_A + (uint32_t)((wMr + (l & 15)) * ROWB) + kHalf;
    const uint32_t b1B = sb + T_B1 + (uint32_t)((wNc + (l & 15)) * ROWB) + kHalf;
    const uint32_t b0B = b1B + TILE_B;

    issue();
    for (int t = 0; t < NT; t++) {
        CP_WAIT0();
        __syncthreads();
        if (t + 1 < NT) issue();

        const uint32_t stb = (uint32_t)((t & 1) << 15);
#pragma unroll
        for (int s2 = 0; s2 < 2; s2++) {
            const uint32_t off = stb + (uint32_t)(s2 * 32);
            uint32_t bh[2][4], bl[2][4];
#pragma unroll
            for (int nj = 0; nj < 2; nj++) {
                ldmx4(bh[nj], b1B + off + (uint32_t)(nj * 16 * ROWB));
                ldmx4(bl[nj], b0B + off + (uint32_t)(nj * 16 * ROWB));
            }
#pragma unroll
            for (int mi = 0; mi < 4; mi++) {
                uint32_t af[4];
                ldmx4(af, aB + off + (uint32_t)(mi * 16 * ROWB));
#pragma unroll
                for (int nj = 0; nj < 2; nj++) {
                    mma16816(acc[mi][nj * 2 + 0], af, bh[nj][0], bh[nj][2]);
                    mma16816(acc[mi][nj * 2 + 1], af, bh[nj][1], bh[nj][3]);
                }
#pragma unroll
                for (int nj = 0; nj < 2; nj++) {
                    mma16816(acc[mi][nj * 2 + 0], af, bl[nj][0], bl[nj][2]);
                    mma16816(acc[mi][nj * 2 + 1], af, bl[nj][1], bl[nj][3]);
                }
            }
        }
        __syncthreads();
    }

    // ---- epilogues ----
    if (MODE == 0) {
        __syncthreads();
        float* red = (float*)smem;  // [128][4]
#pragma unroll
        for (int mi = 0; mi < 4; mi++) {
#pragma unroll
            for (int rr = 0; rr < 2; rr++) {
                const int rloc = wMr + mi * 16 + lq + rr * 8;
                const float* hrow = hmat + (size_t)(row0 + rloc) * DMODEL + col0 + wNc;
                float s = 0.f;
#pragma unroll
                for (int n8 = 0; n8 < 4; n8++) {
                    const int cc = n8 * 8 + lr * 2;
                    float2 h2 = *(const float2*)(hrow + cc);
                    float2 bb = *(const float2*)(bias + col0 + wNc + cc);
                    s += h2.x * (acc[mi][n8][rr * 2 + 0] + bb.x)
                       + h2.y * (acc[mi][n8][rr * 2 + 1] + bb.y);
                }
                s += __shfl_xor_sync(0xffffffffu, s, 1);
                s += __shfl_xor_sync(0xffffffffu, s, 2);
                if (lr == 0) red[rloc * 4 + wN] = s;
            }
        }
        __syncthreads();
        if (tid < 128) {
            float s = red[tid * 4] + red[tid * 4 + 1] + red[tid * 4 + 2] + red[tid * 4 + 3];
            g_logit_part[(size_t)(row0 + tid) * 8 + cb] = s;
        }
    } else if (MODE == 1) {
#pragma unroll
        for (int mi = 0; mi < 4; mi++) {
#pragma unroll
            for (int rr = 0; rr < 2; rr++) {
                const int rg = row0 + wMr + mi * 16 + lq + rr * 8;
                const float al = 1.f / (1.f + __expf(-g_logit[rg] * INV_SQRT_D));
                const float* urow = umat + (size_t)rg * DMODEL + col0 + wNc;
                const float* hrow = hmat + (size_t)rg * DMODEL + col0 + wNc;
                const size_t base1 = (size_t)rg * KMAX + 2 * DMODEL + col0 + wNc;  // ug
                const size_t base2 = (size_t)rg * KMAX + 3 * DMODEL + col0 + wNc;  // h*ug
#pragma unroll
                for (int n8 = 0; n8 < 4; n8++) {
                    const int cc = n8 * 8 + lr * 2;
                    float2 bb = *(const float2*)(bias + col0 + wNc + cc);
                    float2 u2 = *(const float2*)(urow + cc);
                    float2 h2 = *(const float2*)(hrow + cc);
                    float z0 = acc[mi][n8][rr * 2 + 0] + bb.x;
                    float z1 = acc[mi][n8][rr * 2 + 1] + bb.y;
                    float2 o;
                    o.x = al * u2.x / (1.f + __expf(-z0));
                    o.y = al * u2.y / (1.f + __expf(-z1));
                    f16_store2(g_A, base1 + cc, o);
                    f16_store2(g_A, base2 + cc, make_float2(o.x * h2.x, o.y * h2.y));
                }
            }
        }
    } else {
#pragma unroll
        for (int mi = 0; mi < 4; mi++) {
#pragma unroll
            for (int rr = 0; rr < 2; rr++) {
                const int rg = row0 + wMr + mi * 16 + lq + rr * 8;
                float* orow = dst + (size_t)rg * DMODEL + col0 + wNc;
#pragma unroll
                for (int n8 = 0; n8 < 4; n8++) {
                    const int cc = n8 * 8 + lr * 2;
                    float2 bb = *(const float2*)(bias + col0 + wNc + cc);
                    float z0 = acc[mi][n8][rr * 2 + 0] + bb.x;
                    float z1 = acc[mi][n8][rr * 2 + 1] + bb.y;
                    float2 o;
                    o.x = 0.5f * z0 * (1.f + erff(z0 * 0.70710678f));
                    o.y = 0.5f * z1 * (1.f + erff(z1 * 0.70710678f));
                    *(float2*)(orow + cc) = o;
                }
            }
        }
    }
}

extern "C" void kernel_launch(void* const* d_in, const int* in_sizes, int n_in,
                              void* d_out, int out_size) {
    const float* h_t   = (const float*)d_in[0];
    const float* u_t   = (const float*)d_in[1];
    const float* W_a_w = (const float*)d_in[4];
    const float* W_a_b = (const float*)d_in[5];
    const float* W_g_w = (const float*)d_in[6];
    const float* W_g_b = (const float*)d_in[7];
    const float* W_f_w = (const float*)d_in[8];
    const float* W_f_b = (const float*)d_in[9];
    float* out = (float*)d_out;

    cudaFuncSetAttribute(hgemm<0>, cudaFuncAttributeMaxDynamicSharedMemorySize, SMEM_BYTES);
    cudaFuncSetAttribute(hgemm<1>, cudaFuncAttributeMaxDynamicSharedMemorySize, SMEM_BYTES);
    cudaFuncSetAttribute(hgemm<2>, cudaFuncAttributeMaxDynamicSharedMemorySize, SMEM_BYTES);

    __half *Wa1, *Wa0, *Wg1, *Wg0, *Wf1, *Wf0;
    cudaGetSymbolAddress((void**)&Wa1, g_Wa1); cudaGetSymbolAddress((void**)&Wa0, g_Wa0);
    cudaGetSymbolAddress((void**)&Wg1, g_Wg1); cudaGetSymbolAddress((void**)&Wg0, g_Wg0);
    cudaGetSymbolAddress((void**)&Wf1, g_Wf1); cudaGetSymbolAddress((void**)&Wf0, g_Wf0);

    dim3 grid(DMODEL / 128, N_TOK / 128);  // (7, 128)
    const int nConv = (NA_ITEMS + NW_ITEMS + 255) / 256;

    // 5 launches; #4 (hgemm<1>) is the ncu-captured launch
    k_conv_all<<<nConv, 256>>>(h_t, u_t, W_a_w, W_g_w, W_f_w);                   // 1
    hgemm<0><<<grid, 256, SMEM_BYTES>>>(h_t, u_t, Wa1, Wa0, W_a_b, nullptr);     // 2
    k_alpha<<<N_TOK / 8, 256>>>(u_t);                                            // 3
    hgemm<1><<<grid, 256, SMEM_BYTES>>>(h_t, u_t, Wg1, Wg0, W_g_b, nullptr);     // 4
    hgemm<2><<<grid, 256, SMEM_BYTES>>>(h_t, u_t, Wf1, Wf0, W_f_b, out);         // 5
}

// round 11
// speedup vs baseline: 5.0809x; 1.6609x over previous
#include <cuda_runtime.h>
#include <cuda_fp16.h>
#include <math.h>
#include <cstdint>

#define N_TOK 16384
#define DMODEL 896
#define KMAX 3584   // [h | alpha*u | ug | h*ug]
#define INV_SQRT_D 0.03340766f

// ---------------- scratch (device globals) ----------------
__device__ float g_logit_part[N_TOK * 8];
__device__ float g_logit[N_TOK];
__device__ __align__(16) __half g_A[(size_t)N_TOK * KMAX];          // f16 activations
__device__ __align__(16) __half g_Wa[DMODEL * DMODEL];
__device__ __align__(16) __half g_Wg[DMODEL * 2 * DMODEL];
__device__ __align__(16) __half g_Wf[DMODEL * 3 * DMODEL];

// ---------------- helpers ----------------
static __device__ __forceinline__ uint32_t smem_u32(const void* p) {
    uint32_t a;
    asm("{ .reg .u64 t; cvta.to.shared.u64 t, %1; cvt.u32.u64 %0, t; }" : "=r"(a) : "l"(p));
    return a;
}
static __device__ __forceinline__ void cp16(uint32_t s, const void* g) {
    asm volatile("cp.async.cg.shared.global [%0], [%1], 16;" :: "r"(s), "l"(g));
}
#define CP_COMMIT() asm volatile("cp.async.commit_group;" ::: "memory")
#define CP_WAIT0()  asm volatile("cp.async.wait_group 0;" ::: "memory")

static __device__ __forceinline__ void ldmx4(uint32_t* r, uint32_t addr) {
    asm volatile("ldmatrix.sync.aligned.m8n8.x4.shared.b16 {%0,%1,%2,%3}, [%4];"
        : "=r"(r[0]), "=r"(r[1]), "=r"(r[2]), "=r"(r[3]) : "r"(addr));
}
static __device__ __forceinline__ void mma16816(float* c, const uint32_t* a,
                                                uint32_t b0, uint32_t b1) {
    asm volatile("mma.sync.aligned.m16n8k16.row.col.f32.f16.f16.f32 "
        "{%0,%1,%2,%3}, {%4,%5,%6,%7}, {%8,%9}, {%0,%1,%2,%3};"
        : "+f"(c[0]), "+f"(c[1]), "+f"(c[2]), "+f"(c[3])
        : "r"(a[0]), "r"(a[1]), "r"(a[2]), "r"(a[3]), "r"(b0), "r"(b1));
}

// pack float4 -> 4 f16 (8 bytes)
static __device__ __forceinline__ void f16_store4(__half* dst, size_t idx, float4 v) {
    uint32_t p01, p23;
    asm("cvt.rn.f16x2.f32 %0, %1, %2;" : "=r"(p01) : "f"(v.y), "f"(v.x));
    asm("cvt.rn.f16x2.f32 %0, %1, %2;" : "=r"(p23) : "f"(v.w), "f"(v.z));
    *(uint2*)(dst + idx) = make_uint2(p01, p23);
}
static __device__ __forceinline__ void f16_store2(__half* dst, size_t idx, float2 v) {
    uint32_t p;
    asm("cvt.rn.f16x2.f32 %0, %1, %2;" : "=r"(p) : "f"(v.y), "f"(v.x));
    *(uint32_t*)(dst + idx) = p;
}

// ---------------- fused conversion kernel ----------------
#define NA_ITEMS (N_TOK * 224 * 2)
#define NW_ITEMS (DMODEL * (DMODEL + 2 * DMODEL + 3 * DMODEL) / 4)
__global__ void k_conv_all(const float* __restrict__ h, const float* __restrict__ u,
                           const float* __restrict__ wa, const float* __restrict__ wg,
                           const float* __restrict__ wf) {
    int i = blockIdx.x * blockDim.x + threadIdx.x;
    const int half = N_TOK * 224;
    if (i < half) {
        int row = i / 224, c4 = (i % 224) * 4;
        f16_store4(g_A, (size_t)row * KMAX + c4,
                   *(const float4*)(h + (size_t)row * DMODEL + c4));
    } else if (i < 2 * half) {
        int j = i - half;
        int row = j / 224, c4 = (j % 224) * 4;
        f16_store4(g_A, (size_t)row * KMAX + DMODEL + c4,
                   *(const float4*)(u + (size_t)row * DMODEL + c4));
    } else {
        int j = i - 2 * half;
        const int n1 = DMODEL * DMODEL / 4;
        const int n2 = DMODEL * 2 * DMODEL / 4;
        const int n3 = DMODEL * 3 * DMODEL / 4;
        if (j < n1) {
            f16_store4(g_Wa, (size_t)j * 4, ((const float4*)wa)[j]);
        } else if (j < n1 + n2) {
            int k = j - n1;
            f16_store4(g_Wg, (size_t)k * 4, ((const float4*)wg)[k]);
        } else if (j < n1 + n2 + n3) {
            int k = j - n1 - n2;
            f16_store4(g_Wf, (size_t)k * 4, ((const float4*)wf)[k]);
        }
    }
}

// one warp per row: reduce logit partials, compute alpha, write f16 alpha*u into A[896:1792]
__global__ void k_alpha(const float* __restrict__ u) {
    const int row = blockIdx.x * 8 + (threadIdx.x >> 5);
    const int l = threadIdx.x & 31;
    float s = (l < 7) ? g_logit_part[(size_t)row * 8 + l] : 0.f;
    s += __shfl_xor_sync(0xffffffffu, s, 1);
    s += __shfl_xor_sync(0xffffffffu, s, 2);
    s += __shfl_xor_sync(0xffffffffu, s, 4);
    s = __shfl_sync(0xffffffffu, s, 0);
    if (l == 0) g_logit[row] = s;
    const float a = 1.f / (1.f + __expf(-s * INV_SQRT_D));
    const float* ur = u + (size_t)row * DMODEL;
    const size_t base = (size_t)row * KMAX + DMODEL;
#pragma unroll
    for (int j = 0; j < 7; j++) {
        const int c4 = (j * 32 + l) * 4;
        float4 v = *(const float4*)(ur + c4);
        v.x *= a; v.y *= a; v.z *= a; v.w *= a;
        f16_store4(g_A, base + c4, v);
    }
}

// ---------------- f16 single-pass HMMA GEMM (256 thr, 2x4 warps, 64x32 warp tile) ----------------
#define ROWB    80
#define TILE_B  (128 * ROWB)          // 10240
#define T_A     0
#define T_B     TILE_B
#define STAGE_STRIDE 32768            // stage offset = (t&1)<<15
#define SMEM_BYTES (STAGE_STRIDE + 2 * TILE_B)   // 53248; 2 CTAs = 104KB

// MODE 0: K=896 (A = u slot). Epi: logit partials
// MODE 1: K=1792 (A=[h|alpha u]). Epi: ug -> A[1792:2688], h*ug -> A[2688:3584]
// MODE 2: K=2688 (A = {[0:896),[1792:3584)}). Epi: dst = gelu_erf(z)
template <int MODE>
__global__ void __launch_bounds__(256, 2) hgemm(
    const float* __restrict__ hmat, const float* __restrict__ umat,
    const __half* __restrict__ W, const float* __restrict__ bias,
    float* __restrict__ dst)
{
    constexpr int K = (MODE == 0) ? 896 : (MODE == 1 ? 1792 : 2688);
    constexpr int AOFF = (MODE == 0) ? 896 : 0;
    constexpr int NT = K / 32;
    extern __shared__ __align__(16) char smem[];
    const uint32_t sb = smem_u32(smem);

    const int tid = threadIdx.x, wid = tid >> 5, l = tid & 31;
    const int cb = blockIdx.x, rb = blockIdx.y;
    const int row0 = rb * 128, col0 = cb * 128;

    // ---- loader: each thread owns one smem row, 2 of 4 16B chunks (lc in {0,2}) ----
    const int lrow = tid >> 1, lc = (tid & 1) * 2;
    const __half* pA = g_A + (size_t)(row0 + lrow) * KMAX + AOFF + lc * 8;
    const __half* pB = W + (size_t)(col0 + lrow) * K + lc * 8;
    const uint32_t sl = sb + (uint32_t)(lrow * ROWB + lc * 16);

    int nextk = 0;
    auto issue = [&]() {
        const uint32_t so = sl + (uint32_t)((nextk >> 5) & 1) * STAGE_STRIDE;
        cp16(so + T_A, pA);      cp16(so + T_A + 16, pA + 8);
        cp16(so + T_B, pB);      cp16(so + T_B + 16, pB + 8);
        CP_COMMIT();
        nextk += 32;
        int adv = 32;
        if (MODE == 2 && nextk == DMODEL) adv += DMODEL;  // skip alpha*u slot
        pA += adv; pB += 32;
    };

    // ---- warp tiling: 2 (M) x 4 (N); warp tile 64x32 ----
    const int wM = wid & 1, wN = wid >> 1;
    const int wMr = wM * 64, wNc = wN * 32;
    const int lq = l >> 2, lr = l & 3;

    float acc[4][4][4];
#pragma unroll
    for (int a = 0; a < 4; a++)
#pragma unroll
        for (int b = 0; b < 4; b++)
#pragma unroll
            for (int c = 0; c < 4; c++) acc[a][b][c] = 0.f;

    const uint32_t kHalf = (uint32_t)((l >> 4) * 16);
    const uint32_t aB = sb + T_A + (uint32_t)((wMr + (l & 15)) * ROWB) + kHalf;
    const uint32_t bB = sb + T_B + (uint32_t)((wNc + (l & 15)) * ROWB) + kHalf;

    issue();
    for (int t = 0; t < NT; t++) {
        CP_WAIT0();
        __syncthreads();
        if (t + 1 < NT) issue();

        const uint32_t stb = (uint32_t)((t & 1) << 15);
#pragma unroll
        for (int s2 = 0; s2 < 2; s2++) {
            const uint32_t off = stb + (uint32_t)(s2 * 32);
            uint32_t bh[2][4];
#pragma unroll
            for (int nj = 0; nj < 2; nj++)
                ldmx4(bh[nj], bB + off + (uint32_t)(nj * 16 * ROWB));
#pragma unroll
            for (int mi = 0; mi < 4; mi++) {
                uint32_t af[4];
                ldmx4(af, aB + off + (uint32_t)(mi * 16 * ROWB));
#pragma unroll
                for (int nj = 0; nj < 2; nj++) {
                    mma16816(acc[mi][nj * 2 + 0], af, bh[nj][0], bh[nj][2]);
                    mma16816(acc[mi][nj * 2 + 1], af, bh[nj][1], bh[nj][3]);
                }
            }
        }
        __syncthreads();
    }

    // ---- epilogues ----
    if (MODE == 0) {
        __syncthreads();
        float* red = (float*)smem;  // [128][4]
#pragma unroll
        for (int mi = 0; mi < 4; mi++) {
#pragma unroll
            for (int rr = 0; rr < 2; rr++) {
                const int rloc = wMr + mi * 16 + lq + rr * 8;
                const float* hrow = hmat + (size_t)(row0 + rloc) * DMODEL + col0 + wNc;
                float s = 0.f;
#pragma unroll
                for (int n8 = 0; n8 < 4; n8++) {
                    const int cc = n8 * 8 + lr * 2;
                    float2 h2 = *(const float2*)(hrow + cc);
                    float2 bb = *(const float2*)(bias + col0 + wNc + cc);
                    s += h2.x * (acc[mi][n8][rr * 2 + 0] + bb.x)
                       + h2.y * (acc[mi][n8][rr * 2 + 1] + bb.y);
                }
                s += __shfl_xor_sync(0xffffffffu, s, 1);
                s += __shfl_xor_sync(0xffffffffu, s, 2);
                if (lr == 0) red[rloc * 4 + wN] = s;
            }
        }
        __syncthreads();
        if (tid < 128) {
            float s = red[tid * 4] + red[tid * 4 + 1] + red[tid * 4 + 2] + red[tid * 4 + 3];
            g_logit_part[(size_t)(row0 + tid) * 8 + cb] = s;
        }
    } else if (MODE == 1) {
#pragma unroll
        for (int mi = 0; mi < 4; mi++) {
#pragma unroll
            for (int rr = 0; rr < 2; rr++) {
                const int rg = row0 + wMr + mi * 16 + lq + rr * 8;
                const float al = 1.f / (1.f + __expf(-g_logit[rg] * INV_SQRT_D));
                const float* urow = umat + (size_t)rg * DMODEL + col0 + wNc;
                const float* hrow = hmat + (size_t)rg * DMODEL + col0 + wNc;
                const size_t base1 = (size_t)rg * KMAX + 2 * DMODEL + col0 + wNc;  // ug
                const size_t base2 = (size_t)rg * KMAX + 3 * DMODEL + col0 + wNc;  // h*ug
#pragma unroll
                for (int n8 = 0; n8 < 4; n8++) {
                    const int cc = n8 * 8 + lr * 2;
                    float2 bb = *(const float2*)(bias + col0 + wNc + cc);
                    float2 u2 = *(const float2*)(urow + cc);
                    float2 h2 = *(const float2*)(hrow + cc);
                    float z0 = acc[mi][n8][rr * 2 + 0] + bb.x;
                    float z1 = acc[mi][n8][rr * 2 + 1] + bb.y;
                    float2 o;
                    o.x = al * u2.x / (1.f + __expf(-z0));
                    o.y = al * u2.y / (1.f + __expf(-z1));
                    f16_store2(g_A, base1 + cc, o);
                    f16_store2(g_A, base2 + cc, make_float2(o.x * h2.x, o.y * h2.y));
                }
            }
        }
    } else {
#pragma unroll
        for (int mi = 0; mi < 4; mi++) {
#pragma unroll
            for (int rr = 0; rr < 2; rr++) {
                const int rg = row0 + wMr + mi * 16 + lq + rr * 8;
                float* orow = dst + (size_t)rg * DMODEL + col0 + wNc;
#pragma unroll
                for (int n8 = 0; n8 < 4; n8++) {
                    const int cc = n8 * 8 + lr * 2;
                    float2 bb = *(const float2*)(bias + col0 + wNc + cc);
                    float z0 = acc[mi][n8][rr * 2 + 0] + bb.x;
                    float z1 = acc[mi][n8][rr * 2 + 1] + bb.y;
                    float2 o;
                    o.x = 0.5f * z0 * (1.f + erff(z0 * 0.70710678f));
                    o.y = 0.5f * z1 * (1.f + erff(z1 * 0.70710678f));
                    *(float2*)(orow + cc) = o;
                }
            }
        }
    }
}

extern "C" void kernel_launch(void* const* d_in, const int* in_sizes, int n_in,
                              void* d_out, int out_size) {
    const float* h_t   = (const float*)d_in[0];
    const float* u_t   = (const float*)d_in[1];
    const float* W_a_w = (const float*)d_in[4];
    const float* W_a_b = (const float*)d_in[5];
    const float* W_g_w = (const float*)d_in[6];
    const float* W_g_b = (const float*)d_in[7];
    const float* W_f_w = (const float*)d_in[8];
    const float* W_f_b = (const float*)d_in[9];
    float* out = (float*)d_out;

    cudaFuncSetAttribute(hgemm<0>, cudaFuncAttributeMaxDynamicSharedMemorySize, SMEM_BYTES);
    cudaFuncSetAttribute(hgemm<1>, cudaFuncAttributeMaxDynamicSharedMemorySize, SMEM_BYTES);
    cudaFuncSetAttribute(hgemm<2>, cudaFuncAttributeMaxDynamicSharedMemorySize, SMEM_BYTES);

    __half *Wa, *Wg, *Wf;
    cudaGetSymbolAddress((void**)&Wa, g_Wa);
    cudaGetSymbolAddress((void**)&Wg, g_Wg);
    cudaGetSymbolAddress((void**)&Wf, g_Wf);

    dim3 grid(DMODEL / 128, N_TOK / 128);  // (7, 128)
    const int nConv = (NA_ITEMS + NW_ITEMS + 255) / 256;

    // 5 launches; #4 (hgemm<1>) is the ncu-captured launch
    k_conv_all<<<nConv, 256>>>(h_t, u_t, W_a_w, W_g_w, W_f_w);               // 1
    hgemm<0><<<grid, 256, SMEM_BYTES>>>(h_t, u_t, Wa, W_a_b, nullptr);       // 2
    k_alpha<<<N_TOK / 8, 256>>>(u_t);                                        // 3
    hgemm<1><<<grid, 256, SMEM_BYTES>>>(h_t, u_t, Wg, W_g_b, nullptr);       // 4
    hgemm<2><<<grid, 256, SMEM_BYTES>>>(h_t, u_t, Wf, W_f_b, out);           // 5
}